// round 6
// baseline (speedup 1.0000x reference)
#include <cuda_runtime.h>
#include <cuda_bf16.h>
#include <cstdint>
#include <math.h>

#define BB 64
#define HH 256
#define LCC 2048
#define LQQ 256
#define NEGV (-1e30f)

// ---------------- scratch (static __device__; no allocation) ----------------
__device__ float g_S[(size_t)BB * LCC * LQQ];             // S fp32 raw scores
__device__ __nv_bfloat16 g_CT_hi[(size_t)BB * LCC * HH];  // C^T [b][i][h]
__device__ __nv_bfloat16 g_CT_lo[(size_t)BB * LCC * HH];
__device__ __nv_bfloat16 g_CH_hi[(size_t)BB * HH * LCC];  // C [b][h][i]
__device__ __nv_bfloat16 g_CH_lo[(size_t)BB * HH * LCC];
__device__ __nv_bfloat16 g_BQ_hi[(size_t)BB * LQQ * HH];  // (w3*Q+w1)^T [b][j][h]
__device__ __nv_bfloat16 g_BQ_lo[(size_t)BB * LQQ * HH];
__device__ __nv_bfloat16 g_A3_hi[(size_t)BB * 512 * LQQ]; // [Q rows 0-255; Th rows 256-511]
__device__ __nv_bfloat16 g_A3_lo[(size_t)BB * 512 * LQQ];
__device__ __nv_bfloat16 g_ET_hi[(size_t)BB * LQQ * LCC]; // E^T [b][j][i]
__device__ __nv_bfloat16 g_ET_lo[(size_t)BB * LQQ * LCC];
__device__ __nv_bfloat16 g_SR_hi[(size_t)BB * LCC * LQQ]; // S_row [b][i][j]
__device__ __nv_bfloat16 g_SR_lo[(size_t)BB * LCC * LQQ];
__device__ float g_colterm[BB * LQQ];
__device__ float g_pm[BB * 16 * LQQ];   // per-128-row-chunk col max
__device__ float g_ps[BB * 16 * LQQ];   // per-128-row-chunk col expsum
__device__ float g_CM[BB * LQQ];        // final col max
__device__ float g_CSI[BB * LQQ];       // final col 1/sum

// ---------------- helpers ----------------------------------------------------
__device__ __forceinline__ uint32_t smem_u32(const void* p) {
    uint32_t a;
    asm("{ .reg .u64 t; cvta.to.shared.u64 t, %1; cvt.u32.u64 %0, t; }" : "=r"(a) : "l"(p));
    return a;
}
__device__ __forceinline__ void mma16816(float* d, const uint32_t* a, const uint32_t* b) {
    asm volatile(
        "mma.sync.aligned.m16n8k16.row.col.f32.bf16.bf16.f32 "
        "{%0,%1,%2,%3}, {%4,%5,%6,%7}, {%8,%9}, {%0,%1,%2,%3};"
        : "+f"(d[0]), "+f"(d[1]), "+f"(d[2]), "+f"(d[3])
        : "r"(a[0]), "r"(a[1]), "r"(a[2]), "r"(a[3]), "r"(b[0]), "r"(b[1]));
}
__device__ __forceinline__ void ldsm4(uint32_t* r, uint32_t addr) {
    asm volatile("ldmatrix.sync.aligned.m8n8.x4.shared.b16 {%0,%1,%2,%3}, [%4];"
                 : "=r"(r[0]), "=r"(r[1]), "=r"(r[2]), "=r"(r[3])
                 : "r"(addr));
}
__device__ __forceinline__ void cpasync16(uint32_t s, const void* g) {
    asm volatile("cp.async.cg.shared.global [%0], [%1], 16;" ::"r"(s), "l"(g));
}
#define CP_COMMIT() asm volatile("cp.async.commit_group;" ::: "memory")
#define CP_WAIT0() asm volatile("cp.async.wait_group 0;" ::: "memory")

__device__ __forceinline__ void bf16split(float v, __nv_bfloat16& hi, __nv_bfloat16& lo) {
    hi = __float2bfloat16(v);
    lo = __float2bfloat16(v - __bfloat162float(hi));
}
__device__ __forceinline__ void smerge(float& m, float& s, float om, float os) {
    float nm = fmaxf(m, om);
    s = s * __expf(m - nm) + os * __expf(om - nm);
    m = nm;
}

// SMEM stage layout: Ah[128x80B] Al Bh Bl  (pitch 80B = 32 bf16 data + 16B pad)
#define ST_A_L 10240
#define ST_B_H 20480
#define ST_B_L 30720
#define ST_SZ 40960
#define SMEMSZ (2 * ST_SZ)

__device__ __forceinline__ void load_stage(uint32_t smb, int stage,
                                           const __nv_bfloat16* __restrict__ Ah,
                                           const __nv_bfloat16* __restrict__ Al, int lda,
                                           const __nv_bfloat16* __restrict__ Bh,
                                           const __nv_bfloat16* __restrict__ Bl, int ldb,
                                           int kc, int tid) {
    uint32_t s0 = smb + stage * ST_SZ;
#pragma unroll
    for (int t = 0; t < 2; t++) {
        int idx = t * 256 + tid;  // 0..511
        int row = idx >> 2, c = idx & 3;
        uint32_t so = row * 80 + c * 16;
        size_t goa = (size_t)row * lda + kc + c * 8;
        size_t gob = (size_t)row * ldb + kc + c * 8;
        cpasync16(s0 + so, Ah + goa);
        cpasync16(s0 + ST_A_L + so, Al + goa);
        cpasync16(s0 + ST_B_H + so, Bh + gob);
        cpasync16(s0 + ST_B_L + so, Bl + gob);
    }
}

__device__ __forceinline__ void compute_stage(uint32_t smb, int stage, int wm, int wn,
                                              int lane, float acc[4][4][4]) {
    uint32_t s0 = smb + stage * ST_SZ;
    int r = lane & 7, quad = lane >> 3;
#pragma unroll
    for (int ks = 0; ks < 2; ks++) {
        int kb = ks * 32;
        uint32_t ah[4][4], al[4][4], bh[2][4], bl[2][4];
#pragma unroll
        for (int mi = 0; mi < 4; mi++) {
            uint32_t ro = (uint32_t)(wm + mi * 16 + r + ((quad & 1) << 3)) * 80 + kb +
                          ((quad >> 1) << 4);
            ldsm4(ah[mi], s0 + ro);
            ldsm4(al[mi], s0 + ST_A_L + ro);
        }
#pragma unroll
        for (int p = 0; p < 2; p++) {
            uint32_t ro = (uint32_t)(wn + p * 16 + r + ((quad >> 1) << 3)) * 80 + kb +
                          ((quad & 1) << 4);
            ldsm4(bh[p], s0 + ST_B_H + ro);
            ldsm4(bl[p], s0 + ST_B_L + ro);
        }
#pragma unroll
        for (int mi = 0; mi < 4; mi++)
#pragma unroll
            for (int ni = 0; ni < 4; ni++) {
                const uint32_t* bhp = &bh[ni >> 1][(ni & 1) * 2];
                const uint32_t* blp = &bl[ni >> 1][(ni & 1) * 2];
                mma16816(acc[mi][ni], ah[mi], bhp);
                mma16816(acc[mi][ni], al[mi], bhp);
                mma16816(acc[mi][ni], ah[mi], blp);
            }
    }
}

// single-sync double-buffered mainloop
__device__ __forceinline__ void gemm_body(const __nv_bfloat16* Ah, const __nv_bfloat16* Al,
                                          int lda, const __nv_bfloat16* Bh,
                                          const __nv_bfloat16* Bl, int ldb, int K,
                                          uint32_t smb, int tid, int wm, int wn, int lane,
                                          float acc[4][4][4]) {
#pragma unroll
    for (int mi = 0; mi < 4; mi++)
#pragma unroll
        for (int ni = 0; ni < 4; ni++)
#pragma unroll
            for (int k = 0; k < 4; k++) acc[mi][ni][k] = 0.f;

    load_stage(smb, 0, Ah, Al, lda, Bh, Bl, ldb, 0, tid);
    CP_COMMIT();
    int nk = K >> 5;
    int buf = 0;
    for (int kt = 0; kt < nk; kt++) {
        CP_WAIT0();
        __syncthreads();
        if (kt + 1 < nk) {
            load_stage(smb, buf ^ 1, Ah, Al, lda, Bh, Bl, ldb, (kt + 1) * 32, tid);
            CP_COMMIT();
        }
        compute_stage(smb, buf, wm, wn, lane, acc);
        buf ^= 1;
    }
}

// ---------------- GEMM1: S = CT*BQ^T + colterm, + fused col-softmax partials -
__global__ __launch_bounds__(256) void k_mm1(const float* __restrict__ cmask) {
    extern __shared__ char sm[];
    uint32_t smb = smem_u32(sm);
    int tid = threadIdx.x, lane = tid & 31, w = tid >> 5;
    int wm = (w >> 2) * 64, wn = (w & 3) * 32;
    int b = blockIdx.z, bm = blockIdx.y * 128, bn = blockIdx.x * 128;

    const __nv_bfloat16* Ah = g_CT_hi + (size_t)b * LCC * HH + (size_t)bm * HH;
    const __nv_bfloat16* Al = g_CT_lo + (size_t)b * LCC * HH + (size_t)bm * HH;
    const __nv_bfloat16* Bh = g_BQ_hi + (size_t)b * LQQ * HH + (size_t)bn * HH;
    const __nv_bfloat16* Bl = g_BQ_lo + (size_t)b * LQQ * HH + (size_t)bn * HH;

    float acc[4][4][4];
    gemm_body(Ah, Al, HH, Bh, Bl, HH, HH, smb, tid, wm, wn, lane, acc);

    int r0 = lane >> 2, c0 = (lane & 3) * 2;
    float* Sb = g_S + (size_t)b * LCC * LQQ;
    const float* ct = g_colterm + b * LQQ;
    const float* cm = cmask + b * LCC;

    float colm[8], cols[8];
#pragma unroll
    for (int e = 0; e < 8; e++) {
        colm[e] = -INFINITY;
        cols[e] = 0.f;
    }
#pragma unroll
    for (int mi = 0; mi < 4; mi++) {
        int m1 = bm + wm + mi * 16 + r0;
        float cm1 = cm[m1], cm2 = cm[m1 + 8];
#pragma unroll
        for (int ni = 0; ni < 4; ni++) {
            int gn = bn + wn + ni * 8 + c0;
            float ct0 = ct[gn], ct1 = ct[gn + 1];
            float v00 = acc[mi][ni][0] + ct0, v01 = acc[mi][ni][1] + ct1;
            float v10 = acc[mi][ni][2] + ct0, v11 = acc[mi][ni][3] + ct1;
            *reinterpret_cast<float2*>(&Sb[(size_t)m1 * LQQ + gn]) = make_float2(v00, v01);
            *reinterpret_cast<float2*>(&Sb[(size_t)(m1 + 8) * LQQ + gn]) =
                make_float2(v10, v11);
            int e0 = ni * 2, e1 = ni * 2 + 1;
            smerge(colm[e0], cols[e0], v00 * (1.f - cm1) + cm1 * NEGV, 1.f);
            smerge(colm[e1], cols[e1], v01 * (1.f - cm1) + cm1 * NEGV, 1.f);
            smerge(colm[e0], cols[e0], v10 * (1.f - cm2) + cm2 * NEGV, 1.f);
            smerge(colm[e1], cols[e1], v11 * (1.f - cm2) + cm2 * NEGV, 1.f);
        }
    }
    // reduce over 8 lanes sharing the same columns (stride 4, 8, 16)
#pragma unroll
    for (int off = 4; off <= 16; off <<= 1)
#pragma unroll
        for (int e = 0; e < 8; e++) {
            float om = __shfl_xor_sync(~0u, colm[e], off);
            float os = __shfl_xor_sync(~0u, cols[e], off);
            smerge(colm[e], cols[e], om, os);
        }
    // cross-warp (two wm halves) merge via smem (reuse pipeline smem)
    float* redm = reinterpret_cast<float*>(sm);
    float* reds = redm + 256;
    __syncthreads();
    if (lane < 4) {
#pragma unroll
        for (int e = 0; e < 8; e++) {
            int col = wn + (e >> 1) * 8 + lane * 2 + (e & 1);
            redm[(w >> 2) * 128 + col] = colm[e];
            reds[(w >> 2) * 128 + col] = cols[e];
        }
    }
    __syncthreads();
    if (tid < 128) {
        float m0 = redm[tid], s0 = reds[tid];
        smerge(m0, s0, redm[128 + tid], reds[128 + tid]);
        size_t o = ((size_t)b * 16 + blockIdx.y) * LQQ + bn + tid;
        g_pm[o] = m0;
        g_ps[o] = s0;
    }
}

// ---------------- reduce 16 column partials -> CM, 1/CS ----------------------
__global__ void k_colred() {
    int b = blockIdx.x, j = threadIdx.x;
    float M = -INFINITY, S = 0.f;
#pragma unroll
    for (int c = 0; c < 16; c++)
        smerge(M, S, g_pm[((size_t)b * 16 + c) * LQQ + j],
               g_ps[((size_t)b * 16 + c) * LQQ + j]);
    g_CM[b * LQQ + j] = M;
    g_CSI[b * LQQ + j] = 1.f / S;
}

// ---------------- fused row softmax + col normalize (single S read) ----------
__global__ __launch_bounds__(256) void k_sm(const float* __restrict__ qmask,
                                            const float* __restrict__ cmask) {
    __shared__ float qv[LQQ], cmj[LQQ], csj[LQQ];
    __shared__ __nv_bfloat16 th[LQQ * 32], tl[LQQ * 32];
    int b = blockIdx.y, i0 = blockIdx.x * 32;
    int tid = threadIdx.x, warp = tid >> 5, lane = tid & 31;
    qv[tid] = qmask[b * LQQ + tid];
    cmj[tid] = g_CM[b * LQQ + tid];
    csj[tid] = g_CSI[b * LQQ + tid];
    __syncthreads();
#pragma unroll
    for (int r = 0; r < 4; r++) {
        int il = warp * 4 + r;
        int i = i0 + il;
        size_t base = ((size_t)b * LCC + i) * LQQ + lane * 8;
        float v[8];
        *reinterpret_cast<uint4*>(&v[0]) = *reinterpret_cast<const uint4*>(g_S + base);
        *reinterpret_cast<uint4*>(&v[4]) = *reinterpret_cast<const uint4*>(g_S + base + 4);
        float cmi = cmask[b * LCC + i];
        float rv[8];
        float rm = -INFINITY;
#pragma unroll
        for (int t = 0; t < 8; t++) {
            float q = qv[lane * 8 + t];
            rv[t] = v[t] * (1.f - q) + q * NEGV;
            rm = fmaxf(rm, rv[t]);
        }
#pragma unroll
        for (int o = 16; o > 0; o >>= 1) rm = fmaxf(rm, __shfl_xor_sync(~0u, rm, o));
        float rs = 0.f;
#pragma unroll
        for (int t = 0; t < 8; t++) {
            rv[t] = __expf(rv[t] - rm);
            rs += rv[t];
        }
#pragma unroll
        for (int o = 16; o > 0; o >>= 1) rs += __shfl_xor_sync(~0u, rs, o);
        float rinv = 1.f / rs;
        union {
            uint4 u;
            __nv_bfloat16 h[8];
        } ph, pl;
#pragma unroll
        for (int t = 0; t < 8; t++) {
            __nv_bfloat16 hi, lo;
            bf16split(rv[t] * rinv, hi, lo);
            ph.h[t] = hi;
            pl.h[t] = lo;
        }
        *reinterpret_cast<uint4*>(g_SR_hi + base) = ph.u;
        *reinterpret_cast<uint4*>(g_SR_lo + base) = pl.u;
#pragma unroll
        for (int t = 0; t < 8; t++) {
            int j = lane * 8 + t;
            float cv = v[t] * (1.f - cmi) + cmi * NEGV;
            float e = __expf(cv - cmj[j]) * csj[j];
            __nv_bfloat16 hi, lo;
            bf16split(e, hi, lo);
            th[j * 32 + il] = hi;
            tl[j * 32 + il] = lo;
        }
    }
    __syncthreads();
    int j = tid;
    size_t eo = ((size_t)b * LQQ + j) * LCC + i0;
    const uint4* sh = reinterpret_cast<const uint4*>(th + j * 32);
    const uint4* sl = reinterpret_cast<const uint4*>(tl + j * 32);
    uint4* gh = reinterpret_cast<uint4*>(g_ET_hi + eo);
    uint4* gl = reinterpret_cast<uint4*>(g_ET_lo + eo);
#pragma unroll
    for (int q = 0; q < 4; q++) {
        gh[q] = sh[q];
        gl[q] = sl[q];
    }
}

// ---------------- GEMM2: Th[h,j] = sum_i CH[h,i]*ET[j,i] -> A3 rows 256+ -----
__global__ __launch_bounds__(256) void k_mm2() {
    extern __shared__ char sm[];
    uint32_t smb = smem_u32(sm);
    int tid = threadIdx.x, lane = tid & 31, w = tid >> 5;
    int wm = (w >> 2) * 64, wn = (w & 3) * 32;
    int b = blockIdx.z, bm = blockIdx.y * 128, bn = blockIdx.x * 128;

    const __nv_bfloat16* Ah = g_CH_hi + (size_t)b * HH * LCC + (size_t)bm * LCC;
    const __nv_bfloat16* Al = g_CH_lo + (size_t)b * HH * LCC + (size_t)bm * LCC;
    const __nv_bfloat16* Bh = g_ET_hi + (size_t)b * LQQ * LCC + (size_t)bn * LCC;
    const __nv_bfloat16* Bl = g_ET_lo + (size_t)b * LQQ * LCC + (size_t)bn * LCC;

    float acc[4][4][4];
    gemm_body(Ah, Al, LCC, Bh, Bl, LCC, LCC, smb, tid, wm, wn, lane, acc);

    int r0 = lane >> 2, c0 = (lane & 3) * 2;
    __nv_bfloat16* Th = g_A3_hi + (size_t)b * 512 * LQQ;
    __nv_bfloat16* Tl = g_A3_lo + (size_t)b * 512 * LQQ;
#pragma unroll
    for (int mi = 0; mi < 4; mi++)
#pragma unroll
        for (int ni = 0; ni < 4; ni++) {
            int gm = 256 + bm + wm + mi * 16 + r0;
            int gn = bn + wn + ni * 8 + c0;
#pragma unroll
            for (int rr = 0; rr < 2; rr++) {
                __nv_bfloat16 h0, l0, h1, l1;
                bf16split(acc[mi][ni][rr * 2 + 0], h0, l0);
                bf16split(acc[mi][ni][rr * 2 + 1], h1, l1);
                size_t o = (size_t)(gm + rr * 8) * LQQ + gn;
                *reinterpret_cast<__nv_bfloat162*>(&Th[o]) = __nv_bfloat162(h0, h1);
                *reinterpret_cast<__nv_bfloat162*>(&Tl[o]) = __nv_bfloat162(l0, l1);
            }
        }
}

// ---------------- GEMM3: [Ah; Bth] = [Q; Th] * SR^T + fused output epilogue ---
__global__ __launch_bounds__(256) void k_mm3(const float* __restrict__ C,
                                             float* __restrict__ out) {
    extern __shared__ char sm[];
    uint32_t smb = smem_u32(sm);
    int tid = threadIdx.x, lane = tid & 31, w = tid >> 5;
    int wm = (w >> 2) * 64, wn = (w & 3) * 32;
    int b = blockIdx.z, bm = blockIdx.y * 128, bn = blockIdx.x * 128;

    const __nv_bfloat16* Ah = g_A3_hi + (size_t)b * 512 * LQQ + (size_t)bm * LQQ;
    const __nv_bfloat16* Al = g_A3_lo + (size_t)b * 512 * LQQ + (size_t)bm * LQQ;
    const __nv_bfloat16* Bh = g_SR_hi + (size_t)b * LCC * LQQ + (size_t)bn * LQQ;
    const __nv_bfloat16* Bl = g_SR_lo + (size_t)b * LCC * LQQ + (size_t)bn * LQQ;

    float acc[4][4][4];
    gemm_body(Ah, Al, LQQ, Bh, Bl, LQQ, LQQ, smb, tid, wm, wn, lane, acc);

    int r0 = lane >> 2, c0 = (lane & 3) * 2;
    const float* Cb = C + (size_t)b * HH * LCC;
    float* ob = out + (size_t)b * 4 * HH * LCC;
    const size_t CH = (size_t)HH * LCC;
    bool isA = (bm < 256);
#pragma unroll
    for (int mi = 0; mi < 4; mi++)
#pragma unroll
        for (int ni = 0; ni < 4; ni++) {
            int gm = bm + wm + mi * 16 + r0;
            int gn = bn + wn + ni * 8 + c0;
#pragma unroll
            for (int rr = 0; rr < 2; rr++) {
                int row = gm + rr * 8;
                float a0 = acc[mi][ni][rr * 2 + 0];
                float a1 = acc[mi][ni][rr * 2 + 1];
                if (isA) {
                    int h = row;
                    float2 cv = *reinterpret_cast<const float2*>(&Cb[(size_t)h * LCC + gn]);
                    *reinterpret_cast<float2*>(&ob[(size_t)h * LCC + gn]) = cv;
                    *reinterpret_cast<float2*>(&ob[CH + (size_t)h * LCC + gn]) =
                        make_float2(a0, a1);
                    *reinterpret_cast<float2*>(&ob[2 * CH + (size_t)h * LCC + gn]) =
                        make_float2(cv.x * a0, cv.y * a1);
                } else {
                    int h = row - 256;
                    float2 cv = *reinterpret_cast<const float2*>(&Cb[(size_t)h * LCC + gn]);
                    *reinterpret_cast<float2*>(&ob[3 * CH + (size_t)h * LCC + gn]) =
                        make_float2(cv.x * a0, cv.y * a1);
                }
            }
        }
}

// ---------------- colterm[b,j] = sum_h Q[b,h,j] * w2[h] ----------------------
__global__ void k_colterm(const float* __restrict__ Q, const float* __restrict__ lp) {
    int b = blockIdx.x;
    int j = threadIdx.x;
    const float* Qb = Q + (size_t)b * HH * LQQ + j;
    float s = 0.f;
#pragma unroll 8
    for (int h = 0; h < HH; h++) s += Qb[(size_t)h * LQQ] * lp[HH + h];
    g_colterm[b * LQQ + j] = s;
}

// ---------------- prep: C -> CH (straight) + CT (transposed), bf16 split -----
__global__ void k_prep_C(const float* __restrict__ C) {
    __shared__ float t[32][33];
    int b = blockIdx.z;
    int i0 = blockIdx.x * 32;
    int h0 = blockIdx.y * 32;
    int tx = threadIdx.x, ty = threadIdx.y;
    const float* Cb = C + (size_t)b * HH * LCC;
#pragma unroll
    for (int k = 0; k < 4; k++) {
        int h = h0 + ty + 8 * k;
        float v = Cb[(size_t)h * LCC + i0 + tx];
        t[ty + 8 * k][tx] = v;
        __nv_bfloat16 hi, lo;
        bf16split(v, hi, lo);
        size_t o = (size_t)b * HH * LCC + (size_t)h * LCC + i0 + tx;
        g_CH_hi[o] = hi;
        g_CH_lo[o] = lo;
    }
    __syncthreads();
#pragma unroll
    for (int k = 0; k < 4; k++) {
        int i = i0 + ty + 8 * k;
        float v = t[tx][ty + 8 * k];
        __nv_bfloat16 hi, lo;
        bf16split(v, hi, lo);
        size_t o = (size_t)b * LCC * HH + (size_t)i * HH + h0 + tx;
        g_CT_hi[o] = hi;
        g_CT_lo[o] = lo;
    }
}

// ---------------- prep: Q -> A3 rows 0-255 (straight) + BQ transposed --------
__global__ void k_prep_Q(const float* __restrict__ Q, const float* __restrict__ lp) {
    __shared__ float t[32][33];
    int b = blockIdx.z;
    int j0 = blockIdx.x * 32;
    int h0 = blockIdx.y * 32;
    int tx = threadIdx.x, ty = threadIdx.y;
    const float* Qb = Q + (size_t)b * HH * LQQ;
#pragma unroll
    for (int k = 0; k < 4; k++) {
        int h = h0 + ty + 8 * k;
        float v = Qb[(size_t)h * LQQ + j0 + tx];
        t[ty + 8 * k][tx] = v;
        __nv_bfloat16 hi, lo;
        bf16split(v, hi, lo);
        size_t o = (size_t)b * 512 * LQQ + (size_t)h * LQQ + j0 + tx;
        g_A3_hi[o] = hi;
        g_A3_lo[o] = lo;
    }
    __syncthreads();
    float w1 = lp[h0 + tx];
    float w3 = lp[2 * HH + h0 + tx];
#pragma unroll
    for (int k = 0; k < 4; k++) {
        int j = j0 + ty + 8 * k;
        float v = t[tx][ty + 8 * k] * w3 + w1;
        __nv_bfloat16 hi, lo;
        bf16split(v, hi, lo);
        size_t o = (size_t)b * LQQ * HH + (size_t)j * HH + h0 + tx;
        g_BQ_hi[o] = hi;
        g_BQ_lo[o] = lo;
    }
}

// ---------------- launch ------------------------------------------------------
extern "C" void kernel_launch(void* const* d_in, const int* in_sizes, int n_in,
                              void* d_out, int out_size) {
    (void)in_sizes;
    (void)n_in;
    (void)out_size;
    const float* C = (const float*)d_in[0];
    const float* Q = (const float*)d_in[1];
    const float* cmask = (const float*)d_in[2];
    const float* qmask = (const float*)d_in[3];
    const float* lp = (const float*)d_in[4];
    float* out = (float*)d_out;

    cudaFuncSetAttribute(k_mm1, cudaFuncAttributeMaxDynamicSharedMemorySize, SMEMSZ);
    cudaFuncSetAttribute(k_mm2, cudaFuncAttributeMaxDynamicSharedMemorySize, SMEMSZ);
    cudaFuncSetAttribute(k_mm3, cudaFuncAttributeMaxDynamicSharedMemorySize, SMEMSZ);

    k_colterm<<<BB, 256>>>(Q, lp);
    k_prep_C<<<dim3(64, 8, BB), dim3(32, 8)>>>(C);
    k_prep_Q<<<dim3(8, 8, BB), dim3(32, 8)>>>(Q, lp);
    k_mm1<<<dim3(2, 16, BB), 256, SMEMSZ>>>(cmask);
    k_colred<<<BB, 256>>>();
    k_sm<<<dim3(LCC / 32, BB), 256>>>(qmask, cmask);
    k_mm2<<<dim3(2, 2, BB), 256, SMEMSZ>>>();
    k_mm3<<<dim3(16, 4, BB), 256, SMEMSZ>>>(C, out);
}

// round 10
// speedup vs baseline: 1.0360x; 1.0360x over previous
#include <cuda_runtime.h>
#include <cuda_bf16.h>
#include <cstdint>
#include <math.h>

#define BB 64
#define HH 256
#define LCC 2048
#define LQQ 256
#define NEGV (-1e30f)

// ---------------- scratch (static __device__; no allocation) ----------------
__device__ __nv_bfloat16 g_S_hi[(size_t)BB * LCC * LQQ];  // S bf16 hi
__device__ __nv_bfloat16 g_S_lo[(size_t)BB * LCC * LQQ];  // S bf16 lo
__device__ __nv_bfloat16 g_CT_hi[(size_t)BB * LCC * HH];  // C^T [b][i][h]
__device__ __nv_bfloat16 g_CT_lo[(size_t)BB * LCC * HH];
__device__ __nv_bfloat16 g_CH_hi[(size_t)BB * HH * LCC];  // C [b][h][i]
__device__ __nv_bfloat16 g_CH_lo[(size_t)BB * HH * LCC];
__device__ __nv_bfloat16 g_BQ_hi[(size_t)BB * LQQ * HH];  // (w3*Q+w1)^T [b][j][h]
__device__ __nv_bfloat16 g_BQ_lo[(size_t)BB * LQQ * HH];
__device__ __nv_bfloat16 g_A3_hi[(size_t)BB * 512 * LQQ]; // [Q rows 0-255; Th rows 256-511]
__device__ __nv_bfloat16 g_A3_lo[(size_t)BB * 512 * LQQ];
__device__ __nv_bfloat16 g_ET_hi[(size_t)BB * LQQ * LCC]; // E^T [b][j][i]
__device__ __nv_bfloat16 g_ET_lo[(size_t)BB * LQQ * LCC];
__device__ __nv_bfloat16 g_SR_hi[(size_t)BB * LCC * LQQ]; // S_row [b][i][j]
__device__ __nv_bfloat16 g_SR_lo[(size_t)BB * LCC * LQQ];
__device__ float g_colterm[BB * LQQ];
__device__ float g_pm[BB * 8 * LQQ];
__device__ float g_ps[BB * 8 * LQQ];

// ---------------- helpers ----------------------------------------------------
__device__ __forceinline__ uint32_t smem_u32(const void* p) {
    uint32_t a;
    asm("{ .reg .u64 t; cvta.to.shared.u64 t, %1; cvt.u32.u64 %0, t; }" : "=r"(a) : "l"(p));
    return a;
}
__device__ __forceinline__ void mma16816(float* d, const uint32_t* a, const uint32_t* b) {
    asm volatile(
        "mma.sync.aligned.m16n8k16.row.col.f32.bf16.bf16.f32 "
        "{%0,%1,%2,%3}, {%4,%5,%6,%7}, {%8,%9}, {%0,%1,%2,%3};"
        : "+f"(d[0]), "+f"(d[1]), "+f"(d[2]), "+f"(d[3])
        : "r"(a[0]), "r"(a[1]), "r"(a[2]), "r"(a[3]), "r"(b[0]), "r"(b[1]));
}
__device__ __forceinline__ void ldsm4(uint32_t* r, uint32_t addr) {
    asm volatile("ldmatrix.sync.aligned.m8n8.x4.shared.b16 {%0,%1,%2,%3}, [%4];"
                 : "=r"(r[0]), "=r"(r[1]), "=r"(r[2]), "=r"(r[3])
                 : "r"(addr));
}
__device__ __forceinline__ void cpasync16(uint32_t s, const void* g) {
    asm volatile("cp.async.cg.shared.global [%0], [%1], 16;" ::"r"(s), "l"(g));
}
#define CP_COMMIT() asm volatile("cp.async.commit_group;" ::: "memory")
#define CP_WAIT1() asm volatile("cp.async.wait_group 1;" ::: "memory")
#define CP_WAIT0() asm volatile("cp.async.wait_group 0;" ::: "memory")

__device__ __forceinline__ void bf16split(float v, __nv_bfloat16& hi, __nv_bfloat16& lo) {
    hi = __float2bfloat16(v);
    lo = __float2bfloat16(v - __bfloat162float(hi));
}
__device__ __forceinline__ float s_at(size_t idx) {
    return __bfloat162float(g_S_hi[idx]) + __bfloat162float(g_S_lo[idx]);
}

// SMEM stage layout: Ah[128x80B] Al Bh Bl  (pitch 80B = 32 bf16 data + 16B pad)
#define ST_A_L 10240
#define ST_B_H 20480
#define ST_B_L 30720
#define ST_SZ 40960
#define SMEMSZ (2 * ST_SZ)

__device__ __forceinline__ void load_stage(uint32_t smb, int stage,
                                           const __nv_bfloat16* __restrict__ Ah,
                                           const __nv_bfloat16* __restrict__ Al, int lda,
                                           const __nv_bfloat16* __restrict__ Bh,
                                           const __nv_bfloat16* __restrict__ Bl, int ldb,
                                           int kc, int tid) {
    uint32_t s0 = smb + stage * ST_SZ;
#pragma unroll
    for (int t = 0; t < 2; t++) {
        int idx = t * 256 + tid;  // 0..511
        int row = idx >> 2, c = idx & 3;
        uint32_t so = row * 80 + c * 16;
        size_t goa = (size_t)row * lda + kc + c * 8;
        size_t gob = (size_t)row * ldb + kc + c * 8;
        cpasync16(s0 + so, Ah + goa);
        cpasync16(s0 + ST_A_L + so, Al + goa);
        cpasync16(s0 + ST_B_H + so, Bh + gob);
        cpasync16(s0 + ST_B_L + so, Bl + gob);
    }
}

__device__ __forceinline__ void compute_stage(uint32_t smb, int stage, int wm, int wn,
                                              int lane, float acc[4][4][4]) {
    uint32_t s0 = smb + stage * ST_SZ;
    int r = lane & 7, quad = lane >> 3;
#pragma unroll
    for (int ks = 0; ks < 2; ks++) {
        int kb = ks * 32;
        uint32_t ah[4][4], al[4][4], bh[2][4], bl[2][4];
#pragma unroll
        for (int mi = 0; mi < 4; mi++) {
            uint32_t ro = (uint32_t)(wm + mi * 16 + r + ((quad & 1) << 3)) * 80 + kb +
                          ((quad >> 1) << 4);
            ldsm4(ah[mi], s0 + ro);
            ldsm4(al[mi], s0 + ST_A_L + ro);
        }
#pragma unroll
        for (int p = 0; p < 2; p++) {
            uint32_t ro = (uint32_t)(wn + p * 16 + r + ((quad >> 1) << 3)) * 80 + kb +
                          ((quad & 1) << 4);
            ldsm4(bh[p], s0 + ST_B_H + ro);
            ldsm4(bl[p], s0 + ST_B_L + ro);
        }
#pragma unroll
        for (int mi = 0; mi < 4; mi++)
#pragma unroll
            for (int ni = 0; ni < 4; ni++) {
                const uint32_t* bhp = &bh[ni >> 1][(ni & 1) * 2];
                const uint32_t* blp = &bl[ni >> 1][(ni & 1) * 2];
                mma16816(acc[mi][ni], ah[mi], bhp);
                mma16816(acc[mi][ni], al[mi], bhp);
                mma16816(acc[mi][ni], ah[mi], blp);
            }
    }
}

__device__ __forceinline__ void gemm_body(const __nv_bfloat16* Ah, const __nv_bfloat16* Al,
                                          int lda, const __nv_bfloat16* Bh,
                                          const __nv_bfloat16* Bl, int ldb, int K,
                                          uint32_t smb, int tid, int wm, int wn, int lane,
                                          float acc[4][4][4]) {
#pragma unroll
    for (int mi = 0; mi < 4; mi++)
#pragma unroll
        for (int ni = 0; ni < 4; ni++)
#pragma unroll
            for (int k = 0; k < 4; k++) acc[mi][ni][k] = 0.f;

    load_stage(smb, 0, Ah, Al, lda, Bh, Bl, ldb, 0, tid);
    CP_COMMIT();
    int nk = K >> 5;
    int buf = 0;
    for (int kt = 0; kt < nk; kt++) {
        if (kt + 1 < nk) {
            load_stage(smb, buf ^ 1, Ah, Al, lda, Bh, Bl, ldb, (kt + 1) * 32, tid);
            CP_COMMIT();
            CP_WAIT1();
        } else {
            CP_WAIT0();
        }
        __syncthreads();
        compute_stage(smb, buf, wm, wn, lane, acc);
        __syncthreads();
        buf ^= 1;
    }
}

// ---------------- GEMM1: S[i,j] = sum_h CT[i,h]*BQ[j,h] + colterm[j] ---------
__global__ __launch_bounds__(256) void k_mm1() {
    extern __shared__ char sm[];
    uint32_t smb = smem_u32(sm);
    int tid = threadIdx.x, lane = tid & 31, w = tid >> 5;
    int wm = (w >> 2) * 64, wn = (w & 3) * 32;
    int b = blockIdx.z, bm = blockIdx.y * 128, bn = blockIdx.x * 128;

    const __nv_bfloat16* Ah = g_CT_hi + (size_t)b * LCC * HH + (size_t)bm * HH;
    const __nv_bfloat16* Al = g_CT_lo + (size_t)b * LCC * HH + (size_t)bm * HH;
    const __nv_bfloat16* Bh = g_BQ_hi + (size_t)b * LQQ * HH + (size_t)bn * HH;
    const __nv_bfloat16* Bl = g_BQ_lo + (size_t)b * LQQ * HH + (size_t)bn * HH;

    float acc[4][4][4];
    gemm_body(Ah, Al, HH, Bh, Bl, HH, HH, smb, tid, wm, wn, lane, acc);

    int r0 = lane >> 2, c0 = (lane & 3) * 2;
    __nv_bfloat16* Sh = g_S_hi + (size_t)b * LCC * LQQ;
    __nv_bfloat16* Sl = g_S_lo + (size_t)b * LCC * LQQ;
    const float* ct = g_colterm + b * LQQ;
#pragma unroll
    for (int mi = 0; mi < 4; mi++)
#pragma unroll
        for (int ni = 0; ni < 4; ni++) {
            int gm = bm + wm + mi * 16 + r0;
            int gn = bn + wn + ni * 8 + c0;
            float ct0 = ct[gn], ct1 = ct[gn + 1];
#pragma unroll
            for (int rr = 0; rr < 2; rr++) {
                float v0 = acc[mi][ni][rr * 2 + 0] + ct0;
                float v1 = acc[mi][ni][rr * 2 + 1] + ct1;
                __nv_bfloat16 h0, l0, h1, l1;
                bf16split(v0, h0, l0);
                bf16split(v1, h1, l1);
                size_t o = (size_t)(gm + rr * 8) * LQQ + gn;
                *reinterpret_cast<__nv_bfloat162*>(&Sh[o]) = __nv_bfloat162(h0, h1);
                *reinterpret_cast<__nv_bfloat162*>(&Sl[o]) = __nv_bfloat162(l0, l1);
            }
        }
}

// ---------------- column softmax partials ------------------------------------
__global__ void k_colsm_part(const float* __restrict__ cmask) {
    int c = blockIdx.x;
    int b = blockIdx.y;
    int j = threadIdx.x;
    size_t Sb = (size_t)b * LCC * LQQ;
    const float* cm = cmask + b * LCC;
    float m = -INFINITY, s = 0.f;
    int i0 = c * 256;
    for (int r = 0; r < 256; r++) {
        int i = i0 + r;
        float cmi = cm[i];
        float val = s_at(Sb + (size_t)i * LQQ + j) * (1.f - cmi) + cmi * NEGV;
        float nm = fmaxf(m, val);
        s = s * __expf(m - nm) + __expf(val - nm);
        m = nm;
    }
    g_pm[(b * 8 + c) * LQQ + j] = m;
    g_ps[(b * 8 + c) * LQQ + j] = s;
}

// ---------------- column softmax normalize -> E^T [b][j][i] bf16 split -------
__global__ void k_colsm_norm(const float* __restrict__ cmask) {
    int c = blockIdx.x;
    int b = blockIdx.y;
    int j = threadIdx.x;
    float M = -INFINITY;
#pragma unroll
    for (int cc = 0; cc < 8; cc++) M = fmaxf(M, g_pm[(b * 8 + cc) * LQQ + j]);
    float S = 0.f;
#pragma unroll
    for (int cc = 0; cc < 8; cc++)
        S += g_ps[(b * 8 + cc) * LQQ + j] * __expf(g_pm[(b * 8 + cc) * LQQ + j] - M);
    float inv = 1.f / S;
    size_t Sb = (size_t)b * LCC * LQQ;
    const float* cm = cmask + b * LCC;
    int i0 = c * 256;
    size_t eo = (size_t)b * LQQ * LCC + (size_t)j * LCC + i0;
    for (int g8 = 0; g8 < 32; g8++) {
        union {
            uint4 u;
            __nv_bfloat16 h[8];
        } ph, pl;
#pragma unroll
        for (int r = 0; r < 8; r++) {
            int i = i0 + g8 * 8 + r;
            float cmi = cm[i];
            float val = s_at(Sb + (size_t)i * LQQ + j) * (1.f - cmi) + cmi * NEGV;
            float e = __expf(val - M) * inv;
            __nv_bfloat16 hi, lo;
            bf16split(e, hi, lo);
            ph.h[r] = hi;
            pl.h[r] = lo;
        }
        *reinterpret_cast<uint4*>(g_ET_hi + eo + g8 * 8) = ph.u;
        *reinterpret_cast<uint4*>(g_ET_lo + eo + g8 * 8) = pl.u;
    }
}

// ---------------- row softmax -> S_row [b][i][j] bf16 split ------------------
__global__ void k_rowsm(const float* __restrict__ qmask) {
    int warp = threadIdx.x >> 5;
    int lane = threadIdx.x & 31;
    int row = blockIdx.x * 8 + warp;
    int b = row >> 11;
    size_t base = (size_t)row * LQQ;
    const float* qm = qmask + b * LQQ;
    float v[8];
    float m = -INFINITY;
#pragma unroll
    for (int t = 0; t < 8; t++) {
        int j = lane + 32 * t;
        float q = qm[j];
        float x = s_at(base + j);
        v[t] = x * (1.f - q) + q * NEGV;
        m = fmaxf(m, v[t]);
    }
#pragma unroll
    for (int o = 16; o > 0; o >>= 1) m = fmaxf(m, __shfl_xor_sync(0xffffffffu, m, o));
    float s = 0.f;
#pragma unroll
    for (int t = 0; t < 8; t++) {
        v[t] = __expf(v[t] - m);
        s += v[t];
    }
#pragma unroll
    for (int o = 16; o > 0; o >>= 1) s += __shfl_xor_sync(0xffffffffu, s, o);
    float inv = 1.f / s;
#pragma unroll
    for (int t = 0; t < 8; t++) {
        float p = v[t] * inv;
        __nv_bfloat16 hi, lo;
        bf16split(p, hi, lo);
        g_SR_hi[base + lane + 32 * t] = hi;
        g_SR_lo[base + lane + 32 * t] = lo;
    }
}

// ---------------- GEMM2: Th[h,j] = sum_i CH[h,i]*ET[j,i] -> A3 rows 256+ -----
__global__ __launch_bounds__(256) void k_mm2() {
    extern __shared__ char sm[];
    uint32_t smb = smem_u32(sm);
    int tid = threadIdx.x, lane = tid & 31, w = tid >> 5;
    int wm = (w >> 2) * 64, wn = (w & 3) * 32;
    int b = blockIdx.z, bm = blockIdx.y * 128, bn = blockIdx.x * 128;

    const __nv_bfloat16* Ah = g_CH_hi + (size_t)b * HH * LCC + (size_t)bm * LCC;
    const __nv_bfloat16* Al = g_CH_lo + (size_t)b * HH * LCC + (size_t)bm * LCC;
    const __nv_bfloat16* Bh = g_ET_hi + (size_t)b * LQQ * LCC + (size_t)bn * LCC;
    const __nv_bfloat16* Bl = g_ET_lo + (size_t)b * LQQ * LCC + (size_t)bn * LCC;

    float acc[4][4][4];
    gemm_body(Ah, Al, LCC, Bh, Bl, LCC, LCC, smb, tid, wm, wn, lane, acc);

    int r0 = lane >> 2, c0 = (lane & 3) * 2;
    __nv_bfloat16* Th = g_A3_hi + (size_t)b * 512 * LQQ;
    __nv_bfloat16* Tl = g_A3_lo + (size_t)b * 512 * LQQ;
#pragma unroll
    for (int mi = 0; mi < 4; mi++)
#pragma unroll
        for (int ni = 0; ni < 4; ni++) {
            int gm = 256 + bm + wm + mi * 16 + r0;
            int gn = bn + wn + ni * 8 + c0;
#pragma unroll
            for (int rr = 0; rr < 2; rr++) {
                __nv_bfloat16 h0, l0, h1, l1;
                bf16split(acc[mi][ni][rr * 2 + 0], h0, l0);
                bf16split(acc[mi][ni][rr * 2 + 1], h1, l1);
                size_t o = (size_t)(gm + rr * 8) * LQQ + gn;
                *reinterpret_cast<__nv_bfloat162*>(&Th[o]) = __nv_bfloat162(h0, h1);
                *reinterpret_cast<__nv_bfloat162*>(&Tl[o]) = __nv_bfloat162(l0, l1);
            }
        }
}

// ---------------- GEMM3: [Ah; Bth] = [Q; Th] * SR^T + fused output epilogue ---
__global__ __launch_bounds__(256) void k_mm3(const float* __restrict__ C,
                                             float* __restrict__ out) {
    extern __shared__ char sm[];
    uint32_t smb = smem_u32(sm);
    int tid = threadIdx.x, lane = tid & 31, w = tid >> 5;
    int wm = (w >> 2) * 64, wn = (w & 3) * 32;
    int b = blockIdx.z, bm = blockIdx.y * 128, bn = blockIdx.x * 128;

    const __nv_bfloat16* Ah = g_A3_hi + (size_t)b * 512 * LQQ + (size_t)bm * LQQ;
    const __nv_bfloat16* Al = g_A3_lo + (size_t)b * 512 * LQQ + (size_t)bm * LQQ;
    const __nv_bfloat16* Bh = g_SR_hi + (size_t)b * LCC * LQQ + (size_t)bn * LQQ;
    const __nv_bfloat16* Bl = g_SR_lo + (size_t)b * LCC * LQQ + (size_t)bn * LQQ;

    float acc[4][4][4];
    gemm_body(Ah, Al, LQQ, Bh, Bl, LQQ, LQQ, smb, tid, wm, wn, lane, acc);

    int r0 = lane >> 2, c0 = (lane & 3) * 2;
    const float* Cb = C + (size_t)b * HH * LCC;
    float* ob = out + (size_t)b * 4 * HH * LCC;
    const size_t CH = (size_t)HH * LCC;
    bool isA = (bm < 256);
#pragma unroll
    for (int mi = 0; mi < 4; mi++)
#pragma unroll
        for (int ni = 0; ni < 4; ni++) {
            int gm = bm + wm + mi * 16 + r0;
            int gn = bn + wn + ni * 8 + c0;
#pragma unroll
            for (int rr = 0; rr < 2; rr++) {
                int row = gm + rr * 8;
                float a0 = acc[mi][ni][rr * 2 + 0];
                float a1 = acc[mi][ni][rr * 2 + 1];
                if (isA) {
                    int h = row;
                    float2 cv = *reinterpret_cast<const float2*>(&Cb[(size_t)h * LCC + gn]);
                    *reinterpret_cast<float2*>(&ob[(size_t)h * LCC + gn]) = cv;
                    *reinterpret_cast<float2*>(&ob[CH + (size_t)h * LCC + gn]) =
                        make_float2(a0, a1);
                    *reinterpret_cast<float2*>(&ob[2 * CH + (size_t)h * LCC + gn]) =
                        make_float2(cv.x * a0, cv.y * a1);
                } else {
                    int h = row - 256;
                    float2 cv = *reinterpret_cast<const float2*>(&Cb[(size_t)h * LCC + gn]);
                    *reinterpret_cast<float2*>(&ob[3 * CH + (size_t)h * LCC + gn]) =
                        make_float2(cv.x * a0, cv.y * a1);
                }
            }
        }
}

// ---------------- colterm[b,j] = sum_h Q[b,h,j] * w2[h] ----------------------
__global__ void k_colterm(const float* __restrict__ Q, const float* __restrict__ lp) {
    int b = blockIdx.x;
    int j = threadIdx.x;
    const float* Qb = Q + (size_t)b * HH * LQQ + j;
    float s = 0.f;
#pragma unroll 8
    for (int h = 0; h < HH; h++) s += Qb[(size_t)h * LQQ] * lp[HH + h];
    g_colterm[b * LQQ + j] = s;
}

// ---------------- prep: C -> CH (straight) + CT (transposed), bf16 split -----
__global__ void k_prep_C(const float* __restrict__ C) {
    __shared__ float t[32][33];
    int b = blockIdx.z;
    int i0 = blockIdx.x * 32;
    int h0 = blockIdx.y * 32;
    int tx = threadIdx.x, ty = threadIdx.y;
    const float* Cb = C + (size_t)b * HH * LCC;
#pragma unroll
    for (int k = 0; k < 4; k++) {
        int h = h0 + ty + 8 * k;
        float v = Cb[(size_t)h * LCC + i0 + tx];
        t[ty + 8 * k][tx] = v;
        __nv_bfloat16 hi, lo;
        bf16split(v, hi, lo);
        size_t o = (size_t)b * HH * LCC + (size_t)h * LCC + i0 + tx;
        g_CH_hi[o] = hi;
        g_CH_lo[o] = lo;
    }
    __syncthreads();
#pragma unroll
    for (int k = 0; k < 4; k++) {
        int i = i0 + ty + 8 * k;
        float v = t[tx][ty + 8 * k];
        __nv_bfloat16 hi, lo;
        bf16split(v, hi, lo);
        size_t o = (size_t)b * LCC * HH + (size_t)i * HH + h0 + tx;
        g_CT_hi[o] = hi;
        g_CT_lo[o] = lo;
    }
}

// ---------------- prep: Q -> A3 rows 0-255 (straight) + BQ transposed --------
__global__ void k_prep_Q(const float* __restrict__ Q, const float* __restrict__ lp) {
    __shared__ float t[32][33];
    int b = blockIdx.z;
    int j0 = blockIdx.x * 32;
    int h0 = blockIdx.y * 32;
    int tx = threadIdx.x, ty = threadIdx.y;
    const float* Qb = Q + (size_t)b * HH * LQQ;
#pragma unroll
    for (int k = 0; k < 4; k++) {
        int h = h0 + ty + 8 * k;
        float v = Qb[(size_t)h * LQQ + j0 + tx];
        t[ty + 8 * k][tx] = v;
        __nv_bfloat16 hi, lo;
        bf16split(v, hi, lo);
        size_t o = (size_t)b * 512 * LQQ + (size_t)h * LQQ + j0 + tx;
        g_A3_hi[o] = hi;
        g_A3_lo[o] = lo;
    }
    __syncthreads();
    float w1 = lp[h0 + tx];
    float w3 = lp[2 * HH + h0 + tx];
#pragma unroll
    for (int k = 0; k < 4; k++) {
        int j = j0 + ty + 8 * k;
        float v = t[tx][ty + 8 * k] * w3 + w1;
        __nv_bfloat16 hi, lo;
        bf16split(v, hi, lo);
        size_t o = (size_t)b * LQQ * HH + (size_t)j * HH + h0 + tx;
        g_BQ_hi[o] = hi;
        g_BQ_lo[o] = lo;
    }
}

// ---------------- launch ------------------------------------------------------
extern "C" void kernel_launch(void* const* d_in, const int* in_sizes, int n_in,
                              void* d_out, int out_size) {
    (void)in_sizes;
    (void)n_in;
    (void)out_size;
    const float* C = (const float*)d_in[0];
    const float* Q = (const float*)d_in[1];
    const float* cmask = (const float*)d_in[2];
    const float* qmask = (const float*)d_in[3];
    const float* lp = (const float*)d_in[4];
    float* out = (float*)d_out;

    cudaFuncSetAttribute(k_mm1, cudaFuncAttributeMaxDynamicSharedMemorySize, SMEMSZ);
    cudaFuncSetAttribute(k_mm2, cudaFuncAttributeMaxDynamicSharedMemorySize, SMEMSZ);
    cudaFuncSetAttribute(k_mm3, cudaFuncAttributeMaxDynamicSharedMemorySize, SMEMSZ);

    k_colterm<<<BB, 256>>>(Q, lp);
    k_prep_C<<<dim3(64, 8, BB), dim3(32, 8)>>>(C);
    k_prep_Q<<<dim3(8, 8, BB), dim3(32, 8)>>>(Q, lp);
    k_mm1<<<dim3(2, 16, BB), 256, SMEMSZ>>>();
    k_colsm_part<<<dim3(8, BB), 256>>>(cmask);
    k_colsm_norm<<<dim3(8, BB), 256>>>(cmask);
    k_rowsm<<<BB * LCC / 8, 256>>>(qmask);
    k_mm2<<<dim3(2, 2, BB), 256, SMEMSZ>>>();
    k_mm3<<<dim3(16, 4, BB), 256, SMEMSZ>>>(C, out);
}

// round 13
// speedup vs baseline: 1.1014x; 1.0631x over previous
#include <cuda_runtime.h>
#include <cuda_bf16.h>
#include <cstdint>
#include <math.h>

#define BB 64
#define HH 256
#define LCC 2048
#define LQQ 256
#define NEGV (-1e30f)

// ---------------- scratch (static __device__; no allocation) ----------------
__device__ float g_S[(size_t)BB * LCC * LQQ];             // S fp32 raw scores
__device__ __nv_bfloat16 g_CT_hi[(size_t)BB * LCC * HH];  // C^T [b][i][h]
__device__ __nv_bfloat16 g_CT_lo[(size_t)BB * LCC * HH];
__device__ __nv_bfloat16 g_CH_hi[(size_t)BB * HH * LCC];  // C [b][h][i]
__device__ __nv_bfloat16 g_CH_lo[(size_t)BB * HH * LCC];
__device__ __nv_bfloat16 g_BQ_hi[(size_t)BB * LQQ * HH];  // (w3*Q+w1)^T [b][j][h]
__device__ __nv_bfloat16 g_BQ_lo[(size_t)BB * LQQ * HH];
__device__ __nv_bfloat16 g_A3_hi[(size_t)BB * 512 * LQQ]; // [Q rows 0-255; Th rows 256-511]
__device__ __nv_bfloat16 g_A3_lo[(size_t)BB * 512 * LQQ];
__device__ __nv_bfloat16 g_ET_hi[(size_t)BB * LQQ * LCC]; // E^T [b][j][i]
__device__ __nv_bfloat16 g_ET_lo[(size_t)BB * LQQ * LCC];
__device__ __nv_bfloat16 g_SR_hi[(size_t)BB * LCC * LQQ]; // S_row [b][i][j]
__device__ __nv_bfloat16 g_SR_lo[(size_t)BB * LCC * LQQ];
__device__ float g_colterm[BB * LQQ];
__device__ float g_ps[BB * 16 * LQQ];   // per-128-row-chunk col expsum (no max needed)
__device__ float g_CSI[BB * LQQ];       // final col 1/sum

// ---------------- helpers ----------------------------------------------------
__device__ __forceinline__ uint32_t smem_u32(const void* p) {
    uint32_t a;
    asm("{ .reg .u64 t; cvta.to.shared.u64 t, %1; cvt.u32.u64 %0, t; }" : "=r"(a) : "l"(p));
    return a;
}
__device__ __forceinline__ void mma16816(float* d, const uint32_t* a, const uint32_t* b) {
    asm volatile(
        "mma.sync.aligned.m16n8k16.row.col.f32.bf16.bf16.f32 "
        "{%0,%1,%2,%3}, {%4,%5,%6,%7}, {%8,%9}, {%0,%1,%2,%3};"
        : "+f"(d[0]), "+f"(d[1]), "+f"(d[2]), "+f"(d[3])
        : "r"(a[0]), "r"(a[1]), "r"(a[2]), "r"(a[3]), "r"(b[0]), "r"(b[1]));
}
__device__ __forceinline__ void ldsm4(uint32_t* r, uint32_t addr) {
    asm volatile("ldmatrix.sync.aligned.m8n8.x4.shared.b16 {%0,%1,%2,%3}, [%4];"
                 : "=r"(r[0]), "=r"(r[1]), "=r"(r[2]), "=r"(r[3])
                 : "r"(addr));
}
__device__ __forceinline__ void cpasync16(uint32_t s, const void* g) {
    asm volatile("cp.async.cg.shared.global [%0], [%1], 16;" ::"r"(s), "l"(g));
}
#define CP_COMMIT() asm volatile("cp.async.commit_group;" ::: "memory")
#define CP_WAIT1() asm volatile("cp.async.wait_group 1;" ::: "memory")
#define CP_WAIT0() asm volatile("cp.async.wait_group 0;" ::: "memory")

__device__ __forceinline__ void bf16split(float v, __nv_bfloat16& hi, __nv_bfloat16& lo) {
    hi = __float2bfloat16(v);
    lo = __float2bfloat16(v - __bfloat162float(hi));
}

// SMEM stage layout: Ah[128x80B] Al Bh Bl  (pitch 80B = 32 bf16 data + 16B pad)
#define ST_A_L 10240
#define ST_B_H 20480
#define ST_B_L 30720
#define ST_SZ 40960
#define SMEMSZ (2 * ST_SZ)

__device__ __forceinline__ void load_stage(uint32_t smb, int stage,
                                           const __nv_bfloat16* __restrict__ Ah,
                                           const __nv_bfloat16* __restrict__ Al, int lda,
                                           const __nv_bfloat16* __restrict__ Bh,
                                           const __nv_bfloat16* __restrict__ Bl, int ldb,
                                           int kc, int tid) {
    uint32_t s0 = smb + stage * ST_SZ;
#pragma unroll
    for (int t = 0; t < 2; t++) {
        int idx = t * 256 + tid;  // 0..511
        int row = idx >> 2, c = idx & 3;
        uint32_t so = row * 80 + c * 16;
        size_t goa = (size_t)row * lda + kc + c * 8;
        size_t gob = (size_t)row * ldb + kc + c * 8;
        cpasync16(s0 + so, Ah + goa);
        cpasync16(s0 + ST_A_L + so, Al + goa);
        cpasync16(s0 + ST_B_H + so, Bh + gob);
        cpasync16(s0 + ST_B_L + so, Bl + gob);
    }
}

__device__ __forceinline__ void compute_stage(uint32_t smb, int stage, int wm, int wn,
                                              int lane, float acc[4][4][4]) {
    uint32_t s0 = smb + stage * ST_SZ;
    int r = lane & 7, quad = lane >> 3;
#pragma unroll
    for (int ks = 0; ks < 2; ks++) {
        int kb = ks * 32;
        uint32_t ah[4][4], al[4][4], bh[2][4], bl[2][4];
#pragma unroll
        for (int mi = 0; mi < 4; mi++) {
            uint32_t ro = (uint32_t)(wm + mi * 16 + r + ((quad & 1) << 3)) * 80 + kb +
                          ((quad >> 1) << 4);
            ldsm4(ah[mi], s0 + ro);
            ldsm4(al[mi], s0 + ST_A_L + ro);
        }
#pragma unroll
        for (int p = 0; p < 2; p++) {
            uint32_t ro = (uint32_t)(wn + p * 16 + r + ((quad >> 1) << 3)) * 80 + kb +
                          ((quad & 1) << 4);
            ldsm4(bh[p], s0 + ST_B_H + ro);
            ldsm4(bl[p], s0 + ST_B_L + ro);
        }
#pragma unroll
        for (int mi = 0; mi < 4; mi++)
#pragma unroll
            for (int ni = 0; ni < 4; ni++) {
                const uint32_t* bhp = &bh[ni >> 1][(ni & 1) * 2];
                const uint32_t* blp = &bl[ni >> 1][(ni & 1) * 2];
                mma16816(acc[mi][ni], ah[mi], bhp);
                mma16816(acc[mi][ni], al[mi], bhp);
                mma16816(acc[mi][ni], ah[mi], blp);
            }
    }
}

__device__ __forceinline__ void gemm_body(const __nv_bfloat16* Ah, const __nv_bfloat16* Al,
                                          int lda, const __nv_bfloat16* Bh,
                                          const __nv_bfloat16* Bl, int ldb, int K,
                                          uint32_t smb, int tid, int wm, int wn, int lane,
                                          float acc[4][4][4]) {
#pragma unroll
    for (int mi = 0; mi < 4; mi++)
#pragma unroll
        for (int ni = 0; ni < 4; ni++)
#pragma unroll
            for (int k = 0; k < 4; k++) acc[mi][ni][k] = 0.f;

    load_stage(smb, 0, Ah, Al, lda, Bh, Bl, ldb, 0, tid);
    CP_COMMIT();
    int nk = K >> 5;
    int buf = 0;
    for (int kt = 0; kt < nk; kt++) {
        if (kt + 1 < nk) {
            load_stage(smb, buf ^ 1, Ah, Al, lda, Bh, Bl, ldb, (kt + 1) * 32, tid);
            CP_COMMIT();
            CP_WAIT1();
        } else {
            CP_WAIT0();
        }
        __syncthreads();
        compute_stage(smb, buf, wm, wn, lane, acc);
        __syncthreads();
        buf ^= 1;
    }
}

// ---------------- GEMM1: S = CT*BQ^T + colterm, + fused max-free col partials -
__global__ __launch_bounds__(256) void k_mm1(const float* __restrict__ cmask) {
    extern __shared__ char sm[];
    uint32_t smb = smem_u32(sm);
    int tid = threadIdx.x, lane = tid & 31, w = tid >> 5;
    int wm = (w >> 2) * 64, wn = (w & 3) * 32;
    int b = blockIdx.z, bm = blockIdx.y * 128, bn = blockIdx.x * 128;

    const __nv_bfloat16* Ah = g_CT_hi + (size_t)b * LCC * HH + (size_t)bm * HH;
    const __nv_bfloat16* Al = g_CT_lo + (size_t)b * LCC * HH + (size_t)bm * HH;
    const __nv_bfloat16* Bh = g_BQ_hi + (size_t)b * LQQ * HH + (size_t)bn * HH;
    const __nv_bfloat16* Bl = g_BQ_lo + (size_t)b * LQQ * HH + (size_t)bn * HH;

    float acc[4][4][4];
    gemm_body(Ah, Al, HH, Bh, Bl, HH, HH, smb, tid, wm, wn, lane, acc);

    int r0 = lane >> 2, c0 = (lane & 3) * 2;
    float* Sb = g_S + (size_t)b * LCC * LQQ;
    const float* ct = g_colterm + b * LQQ;
    const float* cm = cmask + b * LCC;

    float cols[8];
#pragma unroll
    for (int e = 0; e < 8; e++) cols[e] = 0.f;
#pragma unroll
    for (int mi = 0; mi < 4; mi++) {
        int m1 = bm + wm + mi * 16 + r0;
        float cm1 = cm[m1], cm2 = cm[m1 + 8];
#pragma unroll
        for (int ni = 0; ni < 4; ni++) {
            int gn = bn + wn + ni * 8 + c0;
            float ct0 = ct[gn], ct1 = ct[gn + 1];
            float v00 = acc[mi][ni][0] + ct0, v01 = acc[mi][ni][1] + ct1;
            float v10 = acc[mi][ni][2] + ct0, v11 = acc[mi][ni][3] + ct1;
            *reinterpret_cast<float2*>(&Sb[(size_t)m1 * LQQ + gn]) = make_float2(v00, v01);
            *reinterpret_cast<float2*>(&Sb[(size_t)(m1 + 8) * LQQ + gn]) =
                make_float2(v10, v11);
            int e0 = ni * 2, e1 = ni * 2 + 1;
            cols[e0] += __expf(v00 * (1.f - cm1) + cm1 * NEGV) +
                        __expf(v10 * (1.f - cm2) + cm2 * NEGV);
            cols[e1] += __expf(v01 * (1.f - cm1) + cm1 * NEGV) +
                        __expf(v11 * (1.f - cm2) + cm2 * NEGV);
        }
    }
    // reduce over the 8 lanes sharing each column (strides 4, 8, 16)
#pragma unroll
    for (int off = 4; off <= 16; off <<= 1)
#pragma unroll
        for (int e = 0; e < 8; e++) cols[e] += __shfl_xor_sync(~0u, cols[e], off);
    // merge the two m-warp halves via smem (pipeline smem is free after last sync)
    float* reds = reinterpret_cast<float*>(sm);
    if (lane < 4) {
#pragma unroll
        for (int e = 0; e < 8; e++) {
            int col = wn + (e >> 1) * 8 + lane * 2 + (e & 1);
            reds[(w >> 2) * 128 + col] = cols[e];
        }
    }
    __syncthreads();
    if (tid < 128) {
        float s0 = reds[tid] + reds[128 + tid];
        g_ps[((size_t)b * 16 + blockIdx.y) * LQQ + bn + tid] = s0;
    }
}

// ---------------- reduce 16 column partials -> 1/colsum ----------------------
__global__ void k_colred() {
    int b = blockIdx.x, j = threadIdx.x;
    float S = 0.f;
#pragma unroll
    for (int c = 0; c < 16; c++) S += g_ps[((size_t)b * 16 + c) * LQQ + j];
    g_CSI[b * LQQ + j] = 1.f / S;
}

// ---------------- column softmax normalize (max-free) -> E^T bf16 split ------
__global__ void k_colsm_norm(const float* __restrict__ cmask) {
    int c = blockIdx.x;
    int b = blockIdx.y;
    int j = threadIdx.x;
    float inv = g_CSI[b * LQQ + j];
    const float* Sb = g_S + (size_t)b * LCC * LQQ;
    const float* cm = cmask + b * LCC;
    int i0 = c * 256;
    size_t eo = (size_t)b * LQQ * LCC + (size_t)j * LCC + i0;
    for (int g8 = 0; g8 < 32; g8++) {
        union {
            uint4 u;
            __nv_bfloat16 h[8];
        } ph, pl;
#pragma unroll
        for (int r = 0; r < 8; r++) {
            int i = i0 + g8 * 8 + r;
            float cmi = cm[i];
            float val = Sb[(size_t)i * LQQ + j] * (1.f - cmi) + cmi * NEGV;
            float e = __expf(val) * inv;
            __nv_bfloat16 hi, lo;
            bf16split(e, hi, lo);
            ph.h[r] = hi;
            pl.h[r] = lo;
        }
        *reinterpret_cast<uint4*>(g_ET_hi + eo + g8 * 8) = ph.u;
        *reinterpret_cast<uint4*>(g_ET_lo + eo + g8 * 8) = pl.u;
    }
}

// ---------------- row softmax (max-free) -> S_row bf16 split -----------------
__global__ void k_rowsm(const float* __restrict__ qmask) {
    int warp = threadIdx.x >> 5;
    int lane = threadIdx.x & 31;
    int row = blockIdx.x * 8 + warp;
    int b = row >> 11;
    size_t base = (size_t)row * LQQ;
    const float* qm = qmask + b * LQQ;
    float v[8];
    float s = 0.f;
#pragma unroll
    for (int t = 0; t < 8; t++) {
        int j = lane + 32 * t;
        float q = qm[j];
        float x = g_S[base + j];
        v[t] = __expf(x * (1.f - q) + q * NEGV);
        s += v[t];
    }
#pragma unroll
    for (int o = 16; o > 0; o >>= 1) s += __shfl_xor_sync(0xffffffffu, s, o);
    float inv = 1.f / s;
#pragma unroll
    for (int t = 0; t < 8; t++) {
        float p = v[t] * inv;
        __nv_bfloat16 hi, lo;
        bf16split(p, hi, lo);
        g_SR_hi[base + lane + 32 * t] = hi;
        g_SR_lo[base + lane + 32 * t] = lo;
    }
}

// ---------------- GEMM2: Th[h,j] = sum_i CH[h,i]*ET[j,i] -> A3 rows 256+ -----
__global__ __launch_bounds__(256) void k_mm2() {
    extern __shared__ char sm[];
    uint32_t smb = smem_u32(sm);
    int tid = threadIdx.x, lane = tid & 31, w = tid >> 5;
    int wm = (w >> 2) * 64, wn = (w & 3) * 32;
    int b = blockIdx.z, bm = blockIdx.y * 128, bn = blockIdx.x * 128;

    const __nv_bfloat16* Ah = g_CH_hi + (size_t)b * HH * LCC + (size_t)bm * LCC;
    const __nv_bfloat16* Al = g_CH_lo + (size_t)b * HH * LCC + (size_t)bm * LCC;
    const __nv_bfloat16* Bh = g_ET_hi + (size_t)b * LQQ * LCC + (size_t)bn * LCC;
    const __nv_bfloat16* Bl = g_ET_lo + (size_t)b * LQQ * LCC + (size_t)bn * LCC;

    float acc[4][4][4];
    gemm_body(Ah, Al, LCC, Bh, Bl, LCC, LCC, smb, tid, wm, wn, lane, acc);

    int r0 = lane >> 2, c0 = (lane & 3) * 2;
    __nv_bfloat16* Th = g_A3_hi + (size_t)b * 512 * LQQ;
    __nv_bfloat16* Tl = g_A3_lo + (size_t)b * 512 * LQQ;
#pragma unroll
    for (int mi = 0; mi < 4; mi++)
#pragma unroll
        for (int ni = 0; ni < 4; ni++) {
            int gm = 256 + bm + wm + mi * 16 + r0;
            int gn = bn + wn + ni * 8 + c0;
#pragma unroll
            for (int rr = 0; rr < 2; rr++) {
                __nv_bfloat16 h0, l0, h1, l1;
                bf16split(acc[mi][ni][rr * 2 + 0], h0, l0);
                bf16split(acc[mi][ni][rr * 2 + 1], h1, l1);
                size_t o = (size_t)(gm + rr * 8) * LQQ + gn;
                *reinterpret_cast<__nv_bfloat162*>(&Th[o]) = __nv_bfloat162(h0, h1);
                *reinterpret_cast<__nv_bfloat162*>(&Tl[o]) = __nv_bfloat162(l0, l1);
            }
        }
}

// ---------------- GEMM3: [Ah; Bth] = [Q; Th] * SR^T + fused output epilogue ---
__global__ __launch_bounds__(256) void k_mm3(const float* __restrict__ C,
                                             float* __restrict__ out) {
    extern __shared__ char sm[];
    uint32_t smb = smem_u32(sm);
    int tid = threadIdx.x, lane = tid & 31, w = tid >> 5;
    int wm = (w >> 2) * 64, wn = (w & 3) * 32;
    int b = blockIdx.z, bm = blockIdx.y * 128, bn = blockIdx.x * 128;

    const __nv_bfloat16* Ah = g_A3_hi + (size_t)b * 512 * LQQ + (size_t)bm * LQQ;
    const __nv_bfloat16* Al = g_A3_lo + (size_t)b * 512 * LQQ + (size_t)bm * LQQ;
    const __nv_bfloat16* Bh = g_SR_hi + (size_t)b * LCC * LQQ + (size_t)bn * LQQ;
    const __nv_bfloat16* Bl = g_SR_lo + (size_t)b * LCC * LQQ + (size_t)bn * LQQ;

    float acc[4][4][4];
    gemm_body(Ah, Al, LQQ, Bh, Bl, LQQ, LQQ, smb, tid, wm, wn, lane, acc);

    int r0 = lane >> 2, c0 = (lane & 3) * 2;
    const float* Cb = C + (size_t)b * HH * LCC;
    float* ob = out + (size_t)b * 4 * HH * LCC;
    const size_t CH = (size_t)HH * LCC;
    bool isA = (bm < 256);
#pragma unroll
    for (int mi = 0; mi < 4; mi++)
#pragma unroll
        for (int ni = 0; ni < 4; ni++) {
            int gm = bm + wm + mi * 16 + r0;
            int gn = bn + wn + ni * 8 + c0;
#pragma unroll
            for (int rr = 0; rr < 2; rr++) {
                int row = gm + rr * 8;
                float a0 = acc[mi][ni][rr * 2 + 0];
                float a1 = acc[mi][ni][rr * 2 + 1];
                if (isA) {
                    int h = row;
                    float2 cv = *reinterpret_cast<const float2*>(&Cb[(size_t)h * LCC + gn]);
                    *reinterpret_cast<float2*>(&ob[(size_t)h * LCC + gn]) = cv;
                    *reinterpret_cast<float2*>(&ob[CH + (size_t)h * LCC + gn]) =
                        make_float2(a0, a1);
                    *reinterpret_cast<float2*>(&ob[2 * CH + (size_t)h * LCC + gn]) =
                        make_float2(cv.x * a0, cv.y * a1);
                } else {
                    int h = row - 256;
                    float2 cv = *reinterpret_cast<const float2*>(&Cb[(size_t)h * LCC + gn]);
                    *reinterpret_cast<float2*>(&ob[3 * CH + (size_t)h * LCC + gn]) =
                        make_float2(cv.x * a0, cv.y * a1);
                }
            }
        }
}

// ---------------- colterm[b,j] = sum_h Q[b,h,j] * w2[h] ----------------------
__global__ void k_colterm(const float* __restrict__ Q, const float* __restrict__ lp) {
    int b = blockIdx.x;
    int j = threadIdx.x;
    const float* Qb = Q + (size_t)b * HH * LQQ + j;
    float s = 0.f;
#pragma unroll 8
    for (int h = 0; h < HH; h++) s += Qb[(size_t)h * LQQ] * lp[HH + h];
    g_colterm[b * LQQ + j] = s;
}

// ---------------- prep: C -> CH (straight) + CT (transposed), bf16 split -----
__global__ void k_prep_C(const float* __restrict__ C) {
    __shared__ float t[32][33];
    int b = blockIdx.z;
    int i0 = blockIdx.x * 32;
    int h0 = blockIdx.y * 32;
    int tx = threadIdx.x, ty = threadIdx.y;
    const float* Cb = C + (size_t)b * HH * LCC;
#pragma unroll
    for (int k = 0; k < 4; k++) {
        int h = h0 + ty + 8 * k;
        float v = Cb[(size_t)h * LCC + i0 + tx];
        t[ty + 8 * k][tx] = v;
        __nv_bfloat16 hi, lo;
        bf16split(v, hi, lo);
        size_t o = (size_t)b * HH * LCC + (size_t)h * LCC + i0 + tx;
        g_CH_hi[o] = hi;
        g_CH_lo[o] = lo;
    }
    __syncthreads();
#pragma unroll
    for (int k = 0; k < 4; k++) {
        int i = i0 + ty + 8 * k;
        float v = t[tx][ty + 8 * k];
        __nv_bfloat16 hi, lo;
        bf16split(v, hi, lo);
        size_t o = (size_t)b * LCC * HH + (size_t)i * HH + h0 + tx;
        g_CT_hi[o] = hi;
        g_CT_lo[o] = lo;
    }
}

// ---------------- prep: Q -> A3 rows 0-255 (straight) + BQ transposed --------
__global__ void k_prep_Q(const float* __restrict__ Q, const float* __restrict__ lp) {
    __shared__ float t[32][33];
    int b = blockIdx.z;
    int j0 = blockIdx.x * 32;
    int h0 = blockIdx.y * 32;
    int tx = threadIdx.x, ty = threadIdx.y;
    const float* Qb = Q + (size_t)b * HH * LQQ;
#pragma unroll
    for (int k = 0; k < 4; k++) {
        int h = h0 + ty + 8 * k;
        float v = Qb[(size_t)h * LQQ + j0 + tx];
        t[ty + 8 * k][tx] = v;
        __nv_bfloat16 hi, lo;
        bf16split(v, hi, lo);
        size_t o = (size_t)b * 512 * LQQ + (size_t)h * LQQ + j0 + tx;
        g_A3_hi[o] = hi;
        g_A3_lo[o] = lo;
    }
    __syncthreads();
    float w1 = lp[h0 + tx];
    float w3 = lp[2 * HH + h0 + tx];
#pragma unroll
    for (int k = 0; k < 4; k++) {
        int j = j0 + ty + 8 * k;
        float v = t[tx][ty + 8 * k] * w3 + w1;
        __nv_bfloat16 hi, lo;
        bf16split(v, hi, lo);
        size_t o = (size_t)b * LQQ * HH + (size_t)j * HH + h0 + tx;
        g_BQ_hi[o] = hi;
        g_BQ_lo[o] = lo;
    }
}

// ---------------- launch ------------------------------------------------------
extern "C" void kernel_launch(void* const* d_in, const int* in_sizes, int n_in,
                              void* d_out, int out_size) {
    (void)in_sizes;
    (void)n_in;
    (void)out_size;
    const float* C = (const float*)d_in[0];
    const float* Q = (const float*)d_in[1];
    const float* cmask = (const float*)d_in[2];
    const float* qmask = (const float*)d_in[3];
    const float* lp = (const float*)d_in[4];
    float* out = (float*)d_out;

    cudaFuncSetAttribute(k_mm1, cudaFuncAttributeMaxDynamicSharedMemorySize, SMEMSZ);
    cudaFuncSetAttribute(k_mm2, cudaFuncAttributeMaxDynamicSharedMemorySize, SMEMSZ);
    cudaFuncSetAttribute(k_mm3, cudaFuncAttributeMaxDynamicSharedMemorySize, SMEMSZ);

    k_colterm<<<BB, 256>>>(Q, lp);
    k_prep_C<<<dim3(64, 8, BB), dim3(32, 8)>>>(C);
    k_prep_Q<<<dim3(8, 8, BB), dim3(32, 8)>>>(Q, lp);
    k_mm1<<<dim3(2, 16, BB), 256, SMEMSZ>>>(cmask);
    k_colred<<<BB, 256>>>();
    k_colsm_norm<<<dim3(8, BB), 256>>>(cmask);
    k_rowsm<<<BB * LCC / 8, 256>>>(qmask);
    k_mm2<<<dim3(2, 2, BB), 256, SMEMSZ>>>();
    k_mm3<<<dim3(16, 4, BB), 256, SMEMSZ>>>(C, out);
}